// round 2
// baseline (speedup 1.0000x reference)
#include <cuda_runtime.h>
#include <math.h>
#include <stdint.h>

#define N_NODES 20000
#define N_EDGES 640000
#define HDIM    128
#define GDIM    50
#define NLAYERS 6
#define NGRAPH  64
#define CUTOFF  10.0f
#define LOG2F_  0.69314718055994531f
#define PI_     3.14159265358979323846f

// ---------------- device scratch (allocation-free rule: device globals) ----
static __device__ __align__(16) float g_h[N_NODES * HDIM];     // 10.24 MB
static __device__ __align__(16) float g_xf[N_NODES * HDIM];    // 10.24 MB
static __device__ __align__(16) float g_agg[N_NODES * HDIM];   // 10.24 MB
static __device__ __align__(16) float g_d[N_EDGES];            // 2.56 MB
static __device__ __align__(16) float g_C[N_EDGES];            // 2.56 MB
static __device__ __align__(16) float g_ea[(size_t)N_EDGES * GDIM]; // 128 MB (tf32-rounded)
static __device__ __align__(16) float g_sums[NGRAPH * HDIM];
static __device__ float g_cnt[NGRAPH];

// TF32 round-to-nearest (emulates tensor-core input rounding used by the
// reference's JAX/XLA f32 matmuls at Precision.DEFAULT on GPU).
__device__ __forceinline__ float tf32r(float x) {
    uint32_t r;
    asm("cvt.rna.tf32.f32 %0, %1;" : "=r"(r) : "f"(x));
    return __uint_as_float(r);
}
__device__ __forceinline__ float4 tf32r4(float4 v) {
    v.x = tf32r(v.x); v.y = tf32r(v.y); v.z = tf32r(v.z); v.w = tf32r(v.w);
    return v;
}

__device__ __forceinline__ float sspf(float x) {
    // shifted softplus, precise: max(x,0) + log1p(exp(-|x|)) - log(2)
    return fmaxf(x, 0.f) + log1pf(expf(-fabsf(x))) - LOG2F_;
}

// ---------------- precompute kernels ---------------------------------------
__global__ void init_h_kernel(const int* __restrict__ z,
                              const float* __restrict__ emb) {
    int i = blockIdx.x * blockDim.x + threadIdx.x;
    if (i >= N_NODES * HDIM) return;
    int n = i >> 7, j = i & 127;
    g_h[i] = emb[z[n] * HDIM + j];
}

__global__ void dist_kernel(const int* __restrict__ src,
                            const int* __restrict__ dst,
                            const float* __restrict__ pos) {
    int e = blockIdx.x * blockDim.x + threadIdx.x;
    if (e >= N_EDGES) return;
    int s = src[e], t = dst[e];
    float dx = pos[s * 3 + 0] - pos[t * 3 + 0];
    float dy = pos[s * 3 + 1] - pos[t * 3 + 1];
    float dz = pos[s * 3 + 2] - pos[t * 3 + 2];
    float d = sqrtf(dx * dx + dy * dy + dz * dz);
    g_d[e] = d;
    g_C[e] = 0.5f * (cosf(d * (PI_ / CUTOFF)) + 1.0f);
}

__global__ void gauss_kernel() {
    int i = blockIdx.x * blockDim.x + threadIdx.x;
    if (i >= N_EDGES * GDIM) return;
    int e = i / GDIM;
    int g = i - e * GDIM;
    const float step = CUTOFF / (GDIM - 1);
    const float coeff = -0.5f / (step * step);
    float diff = g_d[e] - g * step;
    // precise expf, then TF32-round: g_ea is only ever a matmul operand
    g_ea[i] = tf32r(expf(coeff * diff * diff));
}

// ---------------- xf = h @ conv_w1[l]  (N x 128 @ 128 x 128) ---------------
__global__ __launch_bounds__(128) void matvec_kernel(const float* __restrict__ w) {
    constexpr int NT = 16;
    extern __shared__ float w_s[];                // 16384 floats = 64 KB
    __shared__ float in_s[NT * 128];
    int tid = threadIdx.x;
    for (int i = tid; i < 16384 / 4; i += 128)
        ((float4*)w_s)[i] = tf32r4(((const float4*)w)[i]);
    int n0 = blockIdx.x * NT;
    for (int i = tid; i < NT * 128 / 4; i += 128)
        ((float4*)in_s)[i] = tf32r4(((const float4*)&g_h[(size_t)n0 * 128])[i]);
    __syncthreads();
    for (int e = 0; e < NT; e++) {
        float acc = 0.f;
        #pragma unroll 16
        for (int k = 0; k < 128; k++)
            acc = fmaf(in_s[e * 128 + k], w_s[k * 128 + tid], acc);
        g_xf[(size_t)(n0 + e) * 128 + tid] = acc;
    }
}

// ---------------- zeroing ---------------------------------------------------
__global__ void zero_agg_kernel() {
    int i = blockIdx.x * blockDim.x + threadIdx.x;
    if (i < N_NODES * HDIM) g_agg[i] = 0.f;
}
__global__ void zero_sums_kernel() {
    int i = blockIdx.x * blockDim.x + threadIdx.x;
    if (i < NGRAPH * HDIM) g_sums[i] = 0.f;
    if (i < NGRAPH) g_cnt[i] = 0.f;
}

// ---------------- the big fused edge kernel --------------------------------
// Per edge: W = (ssp(ea @ w1 + b1) @ w2 + b2) * C ; msg = xf[src]*W ; agg[dst]+=msg
// Persistent blocks, 32 edges/tile, weights resident in SMEM (tf32-rounded).
__global__ __launch_bounds__(256) void edge_kernel(
        const int* __restrict__ src, const int* __restrict__ dst,
        const float* __restrict__ w1, const float* __restrict__ b1,
        const float* __restrict__ w2, const float* __restrict__ b2) {
    extern __shared__ float sm[];
    float* w1_s  = sm;                        // 50*128  = 6400
    float* w2_s  = w1_s + GDIM * 128;         // 128*128 = 16384
    float* hid_s = w2_s + 128 * 128;          // 32*128  = 4096
    float* ea_s  = hid_s + 32 * 128;          // 32*50   = 1600
    __shared__ int   src_s[32];
    __shared__ int   dst_s[32];
    __shared__ float C_s[32];
    __shared__ float b1_s[128];
    __shared__ float b2_s[128];

    int tid = threadIdx.x;

    // load layer weights once (persistent kernel), tf32-rounded
    for (int i = tid; i < GDIM * 128 / 4; i += 256)
        ((float4*)w1_s)[i] = tf32r4(((const float4*)w1)[i]);
    for (int i = tid; i < 128 * 128 / 4; i += 256)
        ((float4*)w2_s)[i] = tf32r4(((const float4*)w2)[i]);
    if (tid < 128) { b1_s[tid] = b1[tid]; b2_s[tid] = b2[tid]; }
    __syncthreads();

    const int ntiles = N_EDGES / 32;
    for (int tile = blockIdx.x; tile < ntiles; tile += gridDim.x) {
        int e0 = tile * 32;
        if (tid < 32) {
            int e = e0 + tid;
            src_s[tid] = src[e];
            dst_s[tid] = dst[e];
            C_s[tid]   = g_C[e];
        }
        for (int i = tid; i < 32 * GDIM / 4; i += 256)
            ((float4*)ea_s)[i] = ((const float4*)&g_ea[(size_t)e0 * GDIM])[i];
        __syncthreads();

        // stage B: hid[e][col] = ssp(ea[e] @ w1 + b1), tf32-rounded for stage C
        {
            int col  = tid & 127;
            int half = tid >> 7;
            float bb = b1_s[col];
            for (int e = half; e < 32; e += 2) {
                float acc = bb;
                const float* ear = &ea_s[e * GDIM];
                #pragma unroll
                for (int g = 0; g < GDIM; g++)
                    acc = fmaf(ear[g], w1_s[g * 128 + col], acc);
                hid_s[e * 128 + col] = tf32r(sspf(acc));
            }
        }
        __syncthreads();

        // stage C: register-blocked [32 x 128] @ [128 x 128] + epilogue
        {
            int tx = tid & 31;    // 32 col-groups of 4
            int wy = tid >> 5;    // 8 warps, 4 edges each
            float acc[4][4];
            #pragma unroll
            for (int i = 0; i < 4; i++)
                #pragma unroll
                for (int j = 0; j < 4; j++) acc[i][j] = 0.f;
            const float* hbase = &hid_s[wy * 4 * 128];
            #pragma unroll 4
            for (int k = 0; k < 128; k++) {
                float4 wv = ((const float4*)&w2_s[k * 128])[tx];
                #pragma unroll
                for (int i = 0; i < 4; i++) {
                    float hv = hbase[i * 128 + k];
                    acc[i][0] = fmaf(hv, wv.x, acc[i][0]);
                    acc[i][1] = fmaf(hv, wv.y, acc[i][1]);
                    acc[i][2] = fmaf(hv, wv.z, acc[i][2]);
                    acc[i][3] = fmaf(hv, wv.w, acc[i][3]);
                }
            }
            float4 b2v = ((const float4*)b2_s)[tx];
            #pragma unroll
            for (int i = 0; i < 4; i++) {
                int e = wy * 4 + i;
                float cc = C_s[e];
                float4 xfv = ((const float4*)&g_xf[(size_t)src_s[e] * 128])[tx];
                float m0 = (acc[i][0] + b2v.x) * cc * xfv.x;
                float m1 = (acc[i][1] + b2v.y) * cc * xfv.y;
                float m2 = (acc[i][2] + b2v.z) * cc * xfv.z;
                float m3 = (acc[i][3] + b2v.w) * cc * xfv.w;
                float* ap = &g_agg[(size_t)dst_s[e] * 128 + tx * 4];
                atomicAdd(ap + 0, m0);
                atomicAdd(ap + 1, m1);
                atomicAdd(ap + 2, m2);
                atomicAdd(ap + 3, m3);
            }
        }
        __syncthreads();
    }
}

// ---------------- node update: h += lin(ssp(agg @ w2 + b2)) ----------------
__global__ __launch_bounds__(128) void node_update_kernel(
        const float* __restrict__ w2, const float* __restrict__ b2,
        const float* __restrict__ lw, const float* __restrict__ lb) {
    constexpr int NT = 16;
    extern __shared__ float sm[];
    float* w2_s = sm;            // 16384
    float* lw_s = sm + 16384;    // 16384
    __shared__ float in_s[NT * 128];
    __shared__ float x_s[NT * 128];
    int tid = threadIdx.x;
    for (int i = tid; i < 4096; i += 128) {
        ((float4*)w2_s)[i] = tf32r4(((const float4*)w2)[i]);
        ((float4*)lw_s)[i] = tf32r4(((const float4*)lw)[i]);
    }
    int n0 = blockIdx.x * NT;
    for (int i = tid; i < NT * 128 / 4; i += 128)
        ((float4*)in_s)[i] = tf32r4(((const float4*)&g_agg[(size_t)n0 * 128])[i]);
    __syncthreads();
    float bb = b2[tid];
    for (int e = 0; e < NT; e++) {
        float acc = bb;
        #pragma unroll 16
        for (int k = 0; k < 128; k++)
            acc = fmaf(in_s[e * 128 + k], w2_s[k * 128 + tid], acc);
        x_s[e * 128 + tid] = tf32r(sspf(acc));
    }
    __syncthreads();
    float lbb = lb[tid];
    for (int e = 0; e < NT; e++) {
        float acc = lbb;
        #pragma unroll 16
        for (int k = 0; k < 128; k++)
            acc = fmaf(x_s[e * 128 + k], lw_s[k * 128 + tid], acc);
        g_h[(size_t)(n0 + e) * 128 + tid] += acc;
    }
}

// ---------------- output head + per-graph sum ------------------------------
__global__ __launch_bounds__(128) void out_kernel(
        const float* __restrict__ w1, const float* __restrict__ b1,
        const float* __restrict__ w2, const float* __restrict__ b2,
        const int* __restrict__ batch) {
    constexpr int NT = 16;
    extern __shared__ float sm[];
    float* w1_s = sm;
    float* w2_s = sm + 16384;
    __shared__ float in_s[NT * 128];
    __shared__ float x_s[NT * 128];
    int tid = threadIdx.x;
    for (int i = tid; i < 4096; i += 128) {
        ((float4*)w1_s)[i] = tf32r4(((const float4*)w1)[i]);
        ((float4*)w2_s)[i] = tf32r4(((const float4*)w2)[i]);
    }
    int n0 = blockIdx.x * NT;
    for (int i = tid; i < NT * 128 / 4; i += 128)
        ((float4*)in_s)[i] = tf32r4(((const float4*)&g_h[(size_t)n0 * 128])[i]);
    __syncthreads();
    float bb1 = b1[tid];
    for (int e = 0; e < NT; e++) {
        float acc = bb1;
        #pragma unroll 16
        for (int k = 0; k < 128; k++)
            acc = fmaf(in_s[e * 128 + k], w1_s[k * 128 + tid], acc);
        x_s[e * 128 + tid] = tf32r(sspf(acc));
    }
    __syncthreads();
    float bb2 = b2[tid];
    for (int e = 0; e < NT; e++) {
        float acc = bb2;
        #pragma unroll 16
        for (int k = 0; k < 128; k++)
            acc = fmaf(x_s[e * 128 + k], w2_s[k * 128 + tid], acc);
        int b = batch[n0 + e];
        atomicAdd(&g_sums[b * 128 + tid], acc);
        if (tid == 0) atomicAdd(&g_cnt[b], 1.0f);
    }
}

__global__ void finalize_kernel(float* __restrict__ out) {
    int i = blockIdx.x * blockDim.x + threadIdx.x;
    if (i >= NGRAPH * HDIM) return;
    out[i] = g_sums[i] / fmaxf(g_cnt[i >> 7], 1.0f);
}

// ---------------- launcher --------------------------------------------------
extern "C" void kernel_launch(void* const* d_in, const int* in_sizes, int n_in,
                              void* d_out, int out_size) {
    const int*   z       = (const int*)d_in[0];
    const float* pos     = (const float*)d_in[1];
    const int*   ei      = (const int*)d_in[2];
    const int*   batch   = (const int*)d_in[3];
    const float* emb     = (const float*)d_in[4];
    const float* mlp_w1  = (const float*)d_in[5];   // [L,50,128]
    const float* mlp_b1  = (const float*)d_in[6];   // [L,128]
    const float* mlp_w2  = (const float*)d_in[7];   // [L,128,128]
    const float* mlp_b2  = (const float*)d_in[8];   // [L,128]
    const float* conv_w1 = (const float*)d_in[9];   // [L,128,128]
    const float* conv_w2 = (const float*)d_in[10];  // [L,128,128]
    const float* conv_b2 = (const float*)d_in[11];  // [L,128]
    const float* lin_w   = (const float*)d_in[12];  // [L,128,128]
    const float* lin_b   = (const float*)d_in[13];  // [L,128]
    const float* out1_w  = (const float*)d_in[14];
    const float* out1_b  = (const float*)d_in[15];
    const float* out2_w  = (const float*)d_in[16];
    const float* out2_b  = (const float*)d_in[17];
    float* out = (float*)d_out;

    const int* src = ei;
    const int* dst = ei + N_EDGES;

    const int EDGE_SMEM = (GDIM * 128 + 128 * 128 + 32 * 128 + 32 * GDIM) * 4; // 113920
    const int MV_SMEM   = 16384 * 4;   // 64 KB
    const int NU_SMEM   = 32768 * 4;   // 128 KB

    cudaFuncSetAttribute(edge_kernel, cudaFuncAttributeMaxDynamicSharedMemorySize, EDGE_SMEM);
    cudaFuncSetAttribute(matvec_kernel, cudaFuncAttributeMaxDynamicSharedMemorySize, MV_SMEM);
    cudaFuncSetAttribute(node_update_kernel, cudaFuncAttributeMaxDynamicSharedMemorySize, NU_SMEM);
    cudaFuncSetAttribute(out_kernel, cudaFuncAttributeMaxDynamicSharedMemorySize, NU_SMEM);

    // precompute: h = emb[z]; d, C; gaussian features
    init_h_kernel<<<(N_NODES * HDIM + 255) / 256, 256>>>(z, emb);
    dist_kernel<<<(N_EDGES + 255) / 256, 256>>>(src, dst, pos);
    gauss_kernel<<<(N_EDGES * GDIM + 255) / 256, 256>>>();

    const int NODE_BLOCKS = N_NODES / 16;   // 1250
    const int EDGE_GRID = 296;              // persistent: 2 blocks/SM target

    for (int l = 0; l < NLAYERS; l++) {
        matvec_kernel<<<NODE_BLOCKS, 128, MV_SMEM>>>(conv_w1 + (size_t)l * 128 * 128);
        zero_agg_kernel<<<(N_NODES * HDIM + 255) / 256, 256>>>();
        edge_kernel<<<EDGE_GRID, 256, EDGE_SMEM>>>(
            src, dst,
            mlp_w1 + (size_t)l * GDIM * 128, mlp_b1 + (size_t)l * 128,
            mlp_w2 + (size_t)l * 128 * 128,  mlp_b2 + (size_t)l * 128);
        node_update_kernel<<<NODE_BLOCKS, 128, NU_SMEM>>>(
            conv_w2 + (size_t)l * 128 * 128, conv_b2 + (size_t)l * 128,
            lin_w + (size_t)l * 128 * 128,   lin_b + (size_t)l * 128);
    }

    zero_sums_kernel<<<(NGRAPH * HDIM + 255) / 256, 256>>>();
    out_kernel<<<NODE_BLOCKS, 128, NU_SMEM>>>(out1_w, out1_b, out2_w, out2_b, batch);
    finalize_kernel<<<(NGRAPH * HDIM + 255) / 256, 256>>>(out);
}

// round 4
// speedup vs baseline: 2.2512x; 2.2512x over previous
#include <cuda_runtime.h>
#include <math.h>
#include <stdint.h>

#define N_NODES 20000
#define N_EDGES 640000
#define HDIM    128
#define GDIM    50
#define GPAD    64
#define NLAYERS 6
#define NGRAPH  64
#define CUTOFF  10.0f
#define LOG2F_  0.69314718055994531f
#define PI_     3.14159265358979323846f

#define EPT        128                 // edges per tile
#define NTILES     (N_EDGES / EPT)     // 5000
#define EA_STRIDE  72                  // 64 + 8 pad (floats)
#define HID_STRIDE 136                 // 128 + 8 pad (floats)

// ---------------- device scratch ----------------
static __device__ __align__(16) float g_h[N_NODES * HDIM];
static __device__ __align__(16) float g_xf[N_NODES * HDIM];
static __device__ __align__(16) float g_agg[N_NODES * HDIM];
static __device__ __align__(16) float g_d[N_EDGES];
static __device__ __align__(16) float g_C[N_EDGES];
static __device__ __align__(16) float g_ea[(size_t)N_EDGES * GPAD]; // column-PERMUTED, tf32
static __device__ __align__(16) float g_sums[NGRAPH * HDIM];
static __device__ float g_cnt[NGRAPH];

// ---------------- helpers ----------------
__device__ __forceinline__ float tf32r(float x) {
    uint32_t r;
    asm("cvt.rna.tf32.f32 %0, %1;" : "=r"(r) : "f"(x));
    return __uint_as_float(r);
}
__device__ __forceinline__ float4 tf32r4(float4 v) {
    v.x = tf32r(v.x); v.y = tf32r(v.y); v.z = tf32r(v.z); v.w = tf32r(v.w);
    return v;
}
// precise ssp for node-side kernels
__device__ __forceinline__ float sspf(float x) {
    return fmaxf(x, 0.f) + log1pf(expf(-fabsf(x))) - LOG2F_;
}
// fast ssp for edge kernel (2 MUFU); abs err ~1e-7, harmless at 1e-3 tol
__device__ __forceinline__ float sspf_fast(float x) {
    return fmaxf(x, 0.f) + __logf(1.f + __expf(-fabsf(x))) - LOG2F_;
}

// m16n8k8 tf32 MMA, fp32 accumulate. a0=lo.x a1=hi.x a2=lo.y a3=hi.y
__device__ __forceinline__ void mma_tf32(float4& d, float2 lo, float2 hi, float2 b) {
    asm volatile(
        "mma.sync.aligned.m16n8k8.row.col.f32.tf32.tf32.f32 "
        "{%0,%1,%2,%3}, {%4,%5,%6,%7}, {%8,%9}, {%0,%1,%2,%3};\n"
        : "+f"(d.x), "+f"(d.y), "+f"(d.z), "+f"(d.w)
        : "r"(__float_as_uint(lo.x)), "r"(__float_as_uint(hi.x)),
          "r"(__float_as_uint(lo.y)), "r"(__float_as_uint(hi.y)),
          "r"(__float_as_uint(b.x)),  "r"(__float_as_uint(b.y)));
}

// in-8-group column permutation: col c -> pos ((c&3)<<1)|((c>>2)&1)
__device__ __forceinline__ int pcol8(int c) {
    return (c & ~7) | (((c & 3) << 1) | ((c >> 2) & 1));
}

// ---------------- precompute kernels ----------------
__global__ void init_h_kernel(const int* __restrict__ z, const float* __restrict__ emb) {
    int i = blockIdx.x * blockDim.x + threadIdx.x;
    if (i >= N_NODES * HDIM) return;
    int n = i >> 7, j = i & 127;
    g_h[i] = emb[z[n] * HDIM + j];
}

__global__ void dist_kernel(const int* __restrict__ src, const int* __restrict__ dst,
                            const float* __restrict__ pos) {
    int e = blockIdx.x * blockDim.x + threadIdx.x;
    if (e >= N_EDGES) return;
    int s = src[e], t = dst[e];
    float dx = pos[s * 3 + 0] - pos[t * 3 + 0];
    float dy = pos[s * 3 + 1] - pos[t * 3 + 1];
    float dz = pos[s * 3 + 2] - pos[t * 3 + 2];
    float d = sqrtf(dx * dx + dy * dy + dz * dz);
    g_d[e] = d;
    g_C[e] = 0.5f * (cosf(d * (PI_ / CUTOFF)) + 1.0f);
}

// gaussian table, stored COLUMN-PERMUTED within 8-groups (matches MMA A-frag loads)
__global__ void gauss_kernel() {
    int i = blockIdx.x * blockDim.x + threadIdx.x;
    if (i >= N_EDGES * GPAD) return;
    int e = i >> 6, p = i & 63;
    int cc = (p & ~7) | (((p >> 1) & 3) | ((p & 1) << 2));  // inverse of pcol8
    const float step = CUTOFF / (GDIM - 1);
    const float coeff = -0.5f / (step * step);
    float v = 0.f;
    if (cc < GDIM) {
        float diff = g_d[e] - cc * step;
        v = tf32r(expf(coeff * diff * diff));
    }
    g_ea[i] = v;
}

// ---------------- xf = h @ conv_w1[l] ----------------
__global__ __launch_bounds__(128) void matvec_kernel(const float* __restrict__ w) {
    constexpr int NT = 16;
    extern __shared__ float w_s[];
    __shared__ float in_s[NT * 128];
    int tid = threadIdx.x;
    for (int i = tid; i < 16384 / 4; i += 128)
        ((float4*)w_s)[i] = tf32r4(((const float4*)w)[i]);
    int n0 = blockIdx.x * NT;
    for (int i = tid; i < NT * 128 / 4; i += 128)
        ((float4*)in_s)[i] = tf32r4(((const float4*)&g_h[(size_t)n0 * 128])[i]);
    __syncthreads();
    float acc[NT];
    #pragma unroll
    for (int e = 0; e < NT; e++) acc[e] = 0.f;
    #pragma unroll 4
    for (int k = 0; k < 128; k++) {
        float wv = w_s[k * 128 + tid];
        #pragma unroll
        for (int e = 0; e < NT; e++)
            acc[e] = fmaf(in_s[e * 128 + k], wv, acc[e]);
    }
    #pragma unroll
    for (int e = 0; e < NT; e++)
        g_xf[(size_t)(n0 + e) * 128 + tid] = acc[e];
}

__global__ void zero_agg_kernel() {
    int i = blockIdx.x * blockDim.x + threadIdx.x;
    if (i < N_NODES * HDIM) g_agg[i] = 0.f;
}
__global__ void zero_sums_kernel() {
    int i = blockIdx.x * blockDim.x + threadIdx.x;
    if (i < NGRAPH * HDIM) g_sums[i] = 0.f;
    if (i < NGRAPH) g_cnt[i] = 0.f;
}

// ---------------- MMA edge kernel ----------------
// per 128-edge tile:
//   C1 = EA[128x64] @ W1[64x128]         (tf32 mma.sync)
//   HID = tf32(ssp(C1 + b1))
//   C2 = HID[128x128] @ W2[128x128]      (tf32 mma.sync)
//   agg[dst] += (C2 + b2) * C * xf[src]  (float2 global atomics)
__global__ __launch_bounds__(256, 1) void edge_mma_kernel(
        const int* __restrict__ src, const int* __restrict__ dst,
        const float* __restrict__ w1, const float* __restrict__ b1,
        const float* __restrict__ w2, const float* __restrict__ b2) {
    extern __shared__ float sm[];
    float*  ea_s  = sm;                                  // 128*72   = 9216
    float*  hid_s = ea_s + 128 * EA_STRIDE;              // 128*136  = 17408
    float2* w1f   = (float2*)(hid_s + 128 * HID_STRIDE); // 16*8*32  = 4096 f2
    float2* w2f   = w1f + 16 * 8 * 32;                   // 16*16*32 = 8192 f2
    float*  b1_s  = (float*)(w2f + 16 * 16 * 32);        // 128
    float*  b2_s  = b1_s + 128;                          // 128
    float*  C_s   = b2_s + 128;                          // 128
    int*    src_s = (int*)(C_s + 128);                   // 128
    int*    dst_s = src_s + 128;                         // 128

    int tid = threadIdx.x;
    int wid = tid >> 5;
    int lid = tid & 31;
    int gid = lid >> 2;     // row group within fragment
    int tg  = lid & 3;      // col group within fragment

    // ---- one-time: biases + B-fragments (exact mma fragment layout) ----
    if (tid < 128) { b1_s[tid] = b1[tid]; b2_s[tid] = b2[tid]; }
    for (int i = tid; i < 16 * 8 * 32; i += 256) {
        int nt = i >> 8, kk = (i >> 5) & 7, l = i & 31;
        int g_ = l >> 2, t_ = l & 3;
        int k0 = kk * 8 + t_, n = nt * 8 + g_;
        float v0 = (k0 < GDIM)     ? tf32r(w1[k0 * 128 + n])       : 0.f;
        float v1 = (k0 + 4 < GDIM) ? tf32r(w1[(k0 + 4) * 128 + n]) : 0.f;
        w1f[i] = make_float2(v0, v1);
    }
    for (int i = tid; i < 16 * 16 * 32; i += 256) {
        int nt = i >> 9, kk = (i >> 5) & 15, l = i & 31;
        int g_ = l >> 2, t_ = l & 3;
        int k0 = kk * 8 + t_, n = nt * 8 + g_;
        w2f[i] = make_float2(tf32r(w2[k0 * 128 + n]), tf32r(w2[(k0 + 4) * 128 + n]));
    }
    __syncthreads();

    int mbase = (wid & 3) * 32;   // 32-row strip
    int nb    = (wid >> 2) * 8;   // 8 n-tiles (64 cols)

    for (int t = blockIdx.x; t < NTILES; t += gridDim.x) {
        int e0 = t * EPT;
        // ---- tile loads ----
        if (tid < 128) {
            src_s[tid] = src[e0 + tid];
            dst_s[tid] = dst[e0 + tid];
            C_s[tid]   = g_C[e0 + tid];
        }
        for (int i = tid; i < 128 * 16; i += 256) {
            int r = i >> 4, c4 = i & 15;
            float4 v = ((const float4*)(g_ea + (size_t)(e0 + r) * GPAD))[c4];
            *(float4*)&ea_s[r * EA_STRIDE + c4 * 4] = v;
        }
        __syncthreads();

        float4 acc[2][8];
        #pragma unroll
        for (int mi = 0; mi < 2; mi++)
            #pragma unroll
            for (int ni = 0; ni < 8; ni++)
                acc[mi][ni] = make_float4(0.f, 0.f, 0.f, 0.f);

        // ---- GEMM1: K=64 (8 k-steps) ----
        {
            const float* r0 = &ea_s[(mbase + gid) * EA_STRIDE + 2 * tg];
            #pragma unroll
            for (int kk = 0; kk < 8; kk++) {
                float2 lo0 = *(const float2*)&r0[kk * 8];
                float2 hi0 = *(const float2*)&r0[kk * 8 + 8 * EA_STRIDE];
                float2 lo1 = *(const float2*)&r0[kk * 8 + 16 * EA_STRIDE];
                float2 hi1 = *(const float2*)&r0[kk * 8 + 24 * EA_STRIDE];
                #pragma unroll
                for (int ni = 0; ni < 8; ni++) {
                    float2 b = w1f[((nb + ni) * 8 + kk) * 32 + lid];
                    mma_tf32(acc[0][ni], lo0, hi0, b);
                    mma_tf32(acc[1][ni], lo1, hi1, b);
                }
            }
        }

        // ---- ssp + scatter HID (column-permuted) ----
        #pragma unroll
        for (int mi = 0; mi < 2; mi++) {
            int ra = mbase + mi * 16 + gid;
            int rb = ra + 8;
            #pragma unroll
            for (int ni = 0; ni < 8; ni++) {
                int colb = (nb + ni) * 8;
                int c0 = colb + 2 * tg;
                float4 v = acc[mi][ni];
                int p0 = pcol8(c0), p1 = pcol8(c0 + 1);
                hid_s[ra * HID_STRIDE + p0] = tf32r(sspf_fast(v.x + b1_s[c0]));
                hid_s[ra * HID_STRIDE + p1] = tf32r(sspf_fast(v.y + b1_s[c0 + 1]));
                hid_s[rb * HID_STRIDE + p0] = tf32r(sspf_fast(v.z + b1_s[c0]));
                hid_s[rb * HID_STRIDE + p1] = tf32r(sspf_fast(v.w + b1_s[c0 + 1]));
            }
        }
        __syncthreads();

        #pragma unroll
        for (int mi = 0; mi < 2; mi++)
            #pragma unroll
            for (int ni = 0; ni < 8; ni++)
                acc[mi][ni] = make_float4(0.f, 0.f, 0.f, 0.f);

        // ---- GEMM2: K=128 (16 k-steps) ----
        {
            const float* r0 = &hid_s[(mbase + gid) * HID_STRIDE + 2 * tg];
            #pragma unroll
            for (int kk = 0; kk < 16; kk++) {
                float2 lo0 = *(const float2*)&r0[kk * 8];
                float2 hi0 = *(const float2*)&r0[kk * 8 + 8 * HID_STRIDE];
                float2 lo1 = *(const float2*)&r0[kk * 8 + 16 * HID_STRIDE];
                float2 hi1 = *(const float2*)&r0[kk * 8 + 24 * HID_STRIDE];
                #pragma unroll
                for (int ni = 0; ni < 8; ni++) {
                    float2 b = w2f[((nb + ni) * 16 + kk) * 32 + lid];
                    mma_tf32(acc[0][ni], lo0, hi0, b);
                    mma_tf32(acc[1][ni], lo1, hi1, b);
                }
            }
        }

        // ---- epilogue: (C2 + b2) * C * xf[src] -> atomic agg[dst] ----
        #pragma unroll
        for (int mi = 0; mi < 2; mi++) {
            int ra = mbase + mi * 16 + gid;
            int rb = ra + 8;
            float Ca = C_s[ra], Cb = C_s[rb];
            const float* xa = &g_xf[(size_t)src_s[ra] * 128];
            const float* xb = &g_xf[(size_t)src_s[rb] * 128];
            float* ga = &g_agg[(size_t)dst_s[ra] * 128];
            float* gb = &g_agg[(size_t)dst_s[rb] * 128];
            #pragma unroll
            for (int ni = 0; ni < 8; ni++) {
                int c0 = (nb + ni) * 8 + 2 * tg;
                float4 v = acc[mi][ni];
                float2 ba = *(const float2*)&b2_s[c0];
                float2 xva = *(const float2*)&xa[c0];
                float2 oa = make_float2((v.x + ba.x) * Ca * xva.x,
                                        (v.y + ba.y) * Ca * xva.y);
                atomicAdd((float2*)&ga[c0], oa);
                float2 xvb = *(const float2*)&xb[c0];
                float2 ob = make_float2((v.z + ba.x) * Cb * xvb.x,
                                        (v.w + ba.y) * Cb * xvb.y);
                atomicAdd((float2*)&gb[c0], ob);
            }
        }
        __syncthreads();
    }
}

// ---------------- node update: h += lin(ssp(agg @ w2 + b2)) ----------------
__global__ __launch_bounds__(128) void node_update_kernel(
        const float* __restrict__ w2, const float* __restrict__ b2,
        const float* __restrict__ lw, const float* __restrict__ lb) {
    constexpr int NT = 16;
    extern __shared__ float sm[];
    float* w2_s = sm;
    float* lw_s = sm + 16384;
    __shared__ float in_s[NT * 128];
    __shared__ float x_s[NT * 128];
    int tid = threadIdx.x;
    for (int i = tid; i < 4096; i += 128) {
        ((float4*)w2_s)[i] = tf32r4(((const float4*)w2)[i]);
        ((float4*)lw_s)[i] = tf32r4(((const float4*)lw)[i]);
    }
    int n0 = blockIdx.x * NT;
    for (int i = tid; i < NT * 128 / 4; i += 128)
        ((float4*)in_s)[i] = tf32r4(((const float4*)&g_agg[(size_t)n0 * 128])[i]);
    __syncthreads();
    float acc[NT];
    float bb = b2[tid];
    #pragma unroll
    for (int e = 0; e < NT; e++) acc[e] = bb;
    #pragma unroll 4
    for (int k = 0; k < 128; k++) {
        float wv = w2_s[k * 128 + tid];
        #pragma unroll
        for (int e = 0; e < NT; e++)
            acc[e] = fmaf(in_s[e * 128 + k], wv, acc[e]);
    }
    #pragma unroll
    for (int e = 0; e < NT; e++)
        x_s[e * 128 + tid] = tf32r(sspf(acc[e]));
    __syncthreads();
    float lbb = lb[tid];
    #pragma unroll
    for (int e = 0; e < NT; e++) acc[e] = lbb;
    #pragma unroll 4
    for (int k = 0; k < 128; k++) {
        float wv = lw_s[k * 128 + tid];
        #pragma unroll
        for (int e = 0; e < NT; e++)
            acc[e] = fmaf(x_s[e * 128 + k], wv, acc[e]);
    }
    #pragma unroll
    for (int e = 0; e < NT; e++)
        g_h[(size_t)(n0 + e) * 128 + tid] += acc[e];
}

// ---------------- output head ----------------
__global__ __launch_bounds__(128) void out_kernel(
        const float* __restrict__ w1, const float* __restrict__ b1,
        const float* __restrict__ w2, const float* __restrict__ b2,
        const int* __restrict__ batch) {
    constexpr int NT = 16;
    extern __shared__ float sm[];
    float* w1_s = sm;
    float* w2_s = sm + 16384;
    __shared__ float in_s[NT * 128];
    __shared__ float x_s[NT * 128];
    int tid = threadIdx.x;
    for (int i = tid; i < 4096; i += 128) {
        ((float4*)w1_s)[i] = tf32r4(((const float4*)w1)[i]);
        ((float4*)w2_s)[i] = tf32r4(((const float4*)w2)[i]);
    }
    int n0 = blockIdx.x * NT;
    for (int i = tid; i < NT * 128 / 4; i += 128)
        ((float4*)in_s)[i] = tf32r4(((const float4*)&g_h[(size_t)n0 * 128])[i]);
    __syncthreads();
    float acc[NT];
    float bb1 = b1[tid];
    #pragma unroll
    for (int e = 0; e < NT; e++) acc[e] = bb1;
    #pragma unroll 4
    for (int k = 0; k < 128; k++) {
        float wv = w1_s[k * 128 + tid];
        #pragma unroll
        for (int e = 0; e < NT; e++)
            acc[e] = fmaf(in_s[e * 128 + k], wv, acc[e]);
    }
    #pragma unroll
    for (int e = 0; e < NT; e++)
        x_s[e * 128 + tid] = tf32r(sspf(acc[e]));
    __syncthreads();
    float bb2 = b2[tid];
    #pragma unroll
    for (int e = 0; e < NT; e++) acc[e] = bb2;
    #pragma unroll 4
    for (int k = 0; k < 128; k++) {
        float wv = w2_s[k * 128 + tid];
        #pragma unroll
        for (int e = 0; e < NT; e++)
            acc[e] = fmaf(x_s[e * 128 + k], wv, acc[e]);
    }
    #pragma unroll
    for (int e = 0; e < NT; e++) {
        int b = batch[n0 + e];
        atomicAdd(&g_sums[b * 128 + tid], acc[e]);
        if (tid == 0) atomicAdd(&g_cnt[b], 1.0f);
    }
}

__global__ void finalize_kernel(float* __restrict__ out) {
    int i = blockIdx.x * blockDim.x + threadIdx.x;
    if (i >= NGRAPH * HDIM) return;
    out[i] = g_sums[i] / fmaxf(g_cnt[i >> 7], 1.0f);
}

// ---------------- launcher ----------------
extern "C" void kernel_launch(void* const* d_in, const int* in_sizes, int n_in,
                              void* d_out, int out_size) {
    const int*   z       = (const int*)d_in[0];
    const float* pos     = (const float*)d_in[1];
    const int*   ei      = (const int*)d_in[2];
    const int*   batch   = (const int*)d_in[3];
    const float* emb     = (const float*)d_in[4];
    const float* mlp_w1  = (const float*)d_in[5];
    const float* mlp_b1  = (const float*)d_in[6];
    const float* mlp_w2  = (const float*)d_in[7];
    const float* mlp_b2  = (const float*)d_in[8];
    const float* conv_w1 = (const float*)d_in[9];
    const float* conv_w2 = (const float*)d_in[10];
    const float* conv_b2 = (const float*)d_in[11];
    const float* lin_w   = (const float*)d_in[12];
    const float* lin_b   = (const float*)d_in[13];
    const float* out1_w  = (const float*)d_in[14];
    const float* out1_b  = (const float*)d_in[15];
    const float* out2_w  = (const float*)d_in[16];
    const float* out2_b  = (const float*)d_in[17];
    float* out = (float*)d_out;

    const int* src = ei;
    const int* dst = ei + N_EDGES;

    // edge kernel smem: ea 9216 + hid 17408 + w1f 8192 + w2f 16384 + misc 640 floats
    const int EDGE_SMEM = (9216 + 17408 + 8192 + 16384 + 640) * 4;  // 207360 B
    const int MV_SMEM   = 16384 * 4;
    const int NU_SMEM   = 32768 * 4;

    cudaFuncSetAttribute(edge_mma_kernel, cudaFuncAttributeMaxDynamicSharedMemorySize, EDGE_SMEM);
    cudaFuncSetAttribute(matvec_kernel, cudaFuncAttributeMaxDynamicSharedMemorySize, MV_SMEM);
    cudaFuncSetAttribute(node_update_kernel, cudaFuncAttributeMaxDynamicSharedMemorySize, NU_SMEM);
    cudaFuncSetAttribute(out_kernel, cudaFuncAttributeMaxDynamicSharedMemorySize, NU_SMEM);

    init_h_kernel<<<(N_NODES * HDIM + 255) / 256, 256>>>(z, emb);
    dist_kernel<<<(N_EDGES + 255) / 256, 256>>>(src, dst, pos);
    gauss_kernel<<<(N_EDGES * GPAD + 255) / 256, 256>>>();

    const int NODE_BLOCKS = N_NODES / 16;
    const int EDGE_GRID = 148;

    for (int l = 0; l < NLAYERS; l++) {
        matvec_kernel<<<NODE_BLOCKS, 128, MV_SMEM>>>(conv_w1 + (size_t)l * 128 * 128);
        zero_agg_kernel<<<(N_NODES * HDIM + 255) / 256, 256>>>();
        edge_mma_kernel<<<EDGE_GRID, 256, EDGE_SMEM>>>(
            src, dst,
            mlp_w1 + (size_t)l * GDIM * 128, mlp_b1 + (size_t)l * 128,
            mlp_w2 + (size_t)l * 128 * 128,  mlp_b2 + (size_t)l * 128);
        node_update_kernel<<<NODE_BLOCKS, 128, NU_SMEM>>>(
            conv_w2 + (size_t)l * 128 * 128, conv_b2 + (size_t)l * 128,
            lin_w + (size_t)l * 128 * 128,   lin_b + (size_t)l * 128);
    }

    zero_sums_kernel<<<(NGRAPH * HDIM + 255) / 256, 256>>>();
    out_kernel<<<NODE_BLOCKS, 128, NU_SMEM>>>(out1_w, out1_b, out2_w, out2_b, batch);
    finalize_kernel<<<(NGRAPH * HDIM + 255) / 256, 256>>>(out);
}

// round 5
// speedup vs baseline: 3.4770x; 1.5445x over previous
#include <cuda_runtime.h>
#include <cuda_fp16.h>
#include <math.h>
#include <stdint.h>

#define N_NODES 20000
#define N_EDGES 640000
#define HDIM    128
#define GDIM    50
#define GPAD    64
#define NLAYERS 6
#define NGRAPH  64
#define CUTOFF  10.0f
#define LOG2F_  0.69314718055994531f
#define PI_     3.14159265358979323846f

#define EPT        128                 // edges per tile
#define NTILES     (N_EDGES / EPT)     // 5000
#define EA_STR     72                  // halves per row (64 + 8 pad)
#define HID_STR    136                 // halves per row (128 + 8 pad)

// ---------------- device scratch ----------------
static __device__ __align__(16) float  g_h[N_NODES * HDIM];
static __device__ __align__(16) float  g_xf[N_NODES * HDIM];
static __device__ __align__(16) float  g_agg[N_NODES * HDIM];
static __device__ __align__(16) float  g_d[N_EDGES];
static __device__ __align__(16) float  g_C[N_EDGES];
static __device__ __align__(16) __half g_ea[(size_t)N_EDGES * GPAD];  // fp16 gaussians
static __device__ __align__(16) float  g_sums[NGRAPH * HDIM];
static __device__ float g_cnt[NGRAPH];

// ---------------- helpers ----------------
__device__ __forceinline__ float tf32r(float x) {
    uint32_t r;
    asm("cvt.rna.tf32.f32 %0, %1;" : "=r"(r) : "f"(x));
    return __uint_as_float(r);
}
__device__ __forceinline__ float4 tf32r4(float4 v) {
    v.x = tf32r(v.x); v.y = tf32r(v.y); v.z = tf32r(v.z); v.w = tf32r(v.w);
    return v;
}
__device__ __forceinline__ float sspf(float x) {
    return fmaxf(x, 0.f) + log1pf(expf(-fabsf(x))) - LOG2F_;
}
__device__ __forceinline__ float sspf_fast(float x) {
    return fmaxf(x, 0.f) + __logf(1.f + __expf(-fabsf(x))) - LOG2F_;
}
__device__ __forceinline__ uint32_t smem_u32(const void* p) {
    uint32_t a;
    asm("{ .reg .u64 t; cvta.to.shared.u64 t, %1; cvt.u32.u64 %0, t; }" : "=r"(a) : "l"(p));
    return a;
}
__device__ __forceinline__ uint32_t f2h2(float lo, float hi) {
    __half2 h = __floats2half2_rn(lo, hi);
    return *reinterpret_cast<uint32_t*>(&h);
}

// fp16 m16n8k16 MMA, fp32 accumulate
__device__ __forceinline__ void mma16816(float4& d, const uint32_t a[4], uint2 b) {
    asm volatile(
        "mma.sync.aligned.m16n8k16.row.col.f32.f16.f16.f32 "
        "{%0,%1,%2,%3}, {%4,%5,%6,%7}, {%8,%9}, {%0,%1,%2,%3};\n"
        : "+f"(d.x), "+f"(d.y), "+f"(d.z), "+f"(d.w)
        : "r"(a[0]), "r"(a[1]), "r"(a[2]), "r"(a[3]), "r"(b.x), "r"(b.y));
}
__device__ __forceinline__ void ldsm4(uint32_t r[4], const void* p) {
    uint32_t a = smem_u32(p);
    asm volatile("ldmatrix.sync.aligned.m8n8.x4.shared.b16 {%0,%1,%2,%3}, [%4];"
        : "=r"(r[0]), "=r"(r[1]), "=r"(r[2]), "=r"(r[3]) : "r"(a));
}

// ---------------- precompute kernels ----------------
__global__ void init_h_kernel(const int* __restrict__ z, const float* __restrict__ emb) {
    int i = blockIdx.x * blockDim.x + threadIdx.x;
    if (i >= N_NODES * HDIM) return;
    int n = i >> 7, j = i & 127;
    g_h[i] = emb[z[n] * HDIM + j];
}

__global__ void dist_kernel(const int* __restrict__ src, const int* __restrict__ dst,
                            const float* __restrict__ pos) {
    int e = blockIdx.x * blockDim.x + threadIdx.x;
    if (e >= N_EDGES) return;
    int s = src[e], t = dst[e];
    float dx = pos[s * 3 + 0] - pos[t * 3 + 0];
    float dy = pos[s * 3 + 1] - pos[t * 3 + 1];
    float dz = pos[s * 3 + 2] - pos[t * 3 + 2];
    float d = sqrtf(dx * dx + dy * dy + dz * dz);
    g_d[e] = d;
    g_C[e] = 0.5f * (cosf(d * (PI_ / CUTOFF)) + 1.0f);
}

__global__ void gauss_kernel() {
    int i = blockIdx.x * blockDim.x + threadIdx.x;
    if (i >= N_EDGES * GPAD) return;
    int e = i >> 6, c = i & 63;
    const float step = CUTOFF / (GDIM - 1);
    const float coeff = -0.5f / (step * step);
    float v = 0.f;
    if (c < GDIM) {
        float diff = g_d[e] - c * step;
        v = expf(coeff * diff * diff);
    }
    g_ea[i] = __float2half_rn(v);
}

// ---------------- xf = h @ conv_w1[l] ----------------
__global__ __launch_bounds__(128) void matvec_kernel(const float* __restrict__ w) {
    constexpr int NT = 16;
    extern __shared__ float w_s[];
    __shared__ float in_s[NT * 128];
    int tid = threadIdx.x;
    for (int i = tid; i < 16384 / 4; i += 128)
        ((float4*)w_s)[i] = tf32r4(((const float4*)w)[i]);
    int n0 = blockIdx.x * NT;
    for (int i = tid; i < NT * 128 / 4; i += 128)
        ((float4*)in_s)[i] = tf32r4(((const float4*)&g_h[(size_t)n0 * 128])[i]);
    __syncthreads();
    float acc[NT];
    #pragma unroll
    for (int e = 0; e < NT; e++) acc[e] = 0.f;
    #pragma unroll 4
    for (int k = 0; k < 128; k++) {
        float wv = w_s[k * 128 + tid];
        #pragma unroll
        for (int e = 0; e < NT; e++)
            acc[e] = fmaf(in_s[e * 128 + k], wv, acc[e]);
    }
    #pragma unroll
    for (int e = 0; e < NT; e++)
        g_xf[(size_t)(n0 + e) * 128 + tid] = acc[e];
}

__global__ void zero_agg_kernel() {
    int i = blockIdx.x * blockDim.x + threadIdx.x;
    if (i < N_NODES * HDIM) g_agg[i] = 0.f;
}
__global__ void zero_sums_kernel() {
    int i = blockIdx.x * blockDim.x + threadIdx.x;
    if (i < NGRAPH * HDIM) g_sums[i] = 0.f;
    if (i < NGRAPH) g_cnt[i] = 0.f;
}

// ---------------- fp16 MMA edge kernel ----------------
// per 128-edge tile:
//   C1 = EA[128x64] @ W1[64x128]         (fp16 mma, fp32 accum)
//   HID = fp16(ssp(C1 + b1))
//   C2 = HID[128x128] @ W2[128x128]      (fp16 mma, fp32 accum)
//   agg[dst] += (C2 + b2) * C * xf[src]  (float2 global atomics)
__global__ __launch_bounds__(256, 2) void edge_mma_kernel(
        const int* __restrict__ src, const int* __restrict__ dst,
        const float* __restrict__ w1, const float* __restrict__ b1,
        const float* __restrict__ w2, const float* __restrict__ b2) {
    extern __shared__ char smraw[];
    __half* ea_s  = (__half*)smraw;                 // 128*72  = 18432 B
    __half* hid_s = ea_s + 128 * EA_STR;            // 128*136 = 34816 B
    uint2*  w1f   = (uint2*)(hid_s + 128 * HID_STR);// 4kt*16nt*32 = 2048 -> 16384 B
    uint2*  w2f   = w1f + 2048;                     // 8kt*16nt*32 = 4096 -> 32768 B
    float*  b1_s  = (float*)(w2f + 4096);           // 128
    float*  b2_s  = b1_s + 128;
    float*  C_s   = b2_s + 128;
    int*    src_s = (int*)(C_s + 128);
    int*    dst_s = src_s + 128;

    int tid = threadIdx.x;
    int wid = tid >> 5;
    int lid = tid & 31;
    int gid = lid >> 2;     // fragment row group
    int tg  = lid & 3;      // fragment col group
    int lrow = lid & 15;            // ldmatrix row offset
    int lcol = (lid >> 4) << 3;     // ldmatrix col offset (halves)

    // ---- one-time: biases + fp16 B-fragments (m16n8k16 layout) ----
    if (tid < 128) { b1_s[tid] = b1[tid]; b2_s[tid] = b2[tid]; }
    for (int i = tid; i < 2048; i += 256) {
        int l = i & 31, kt = (i >> 5) & 3, nt = i >> 7;
        int g_ = l >> 2, t_ = l & 3;
        int k0 = kt * 16 + 2 * t_, n = nt * 8 + g_;
        float v0 = (k0     < GDIM) ? w1[k0 * 128 + n]       : 0.f;
        float v1 = (k0 + 1 < GDIM) ? w1[(k0 + 1) * 128 + n] : 0.f;
        float v2 = (k0 + 8 < GDIM) ? w1[(k0 + 8) * 128 + n] : 0.f;
        float v3 = (k0 + 9 < GDIM) ? w1[(k0 + 9) * 128 + n] : 0.f;
        w1f[i] = make_uint2(f2h2(v0, v1), f2h2(v2, v3));
    }
    for (int i = tid; i < 4096; i += 256) {
        int l = i & 31, kt = (i >> 5) & 7, nt = i >> 8;
        int g_ = l >> 2, t_ = l & 3;
        int k0 = kt * 16 + 2 * t_, n = nt * 8 + g_;
        w2f[i] = make_uint2(f2h2(w2[k0 * 128 + n], w2[(k0 + 1) * 128 + n]),
                            f2h2(w2[(k0 + 8) * 128 + n], w2[(k0 + 9) * 128 + n]));
    }
    __syncthreads();

    int mbase = (wid & 3) * 32;   // 32-row strip
    int nb    = (wid >> 2) * 8;   // 8 n-tiles (64 cols)

    for (int t = blockIdx.x; t < NTILES; t += gridDim.x) {
        int e0 = t * EPT;
        // ---- tile loads ----
        if (tid < 128) {
            src_s[tid] = src[e0 + tid];
            dst_s[tid] = dst[e0 + tid];
            C_s[tid]   = g_C[e0 + tid];
        }
        for (int i = tid; i < 1024; i += 256) {     // 128 rows x 8 uint4
            int r = i >> 3, c8 = i & 7;
            uint4 v = ((const uint4*)(g_ea + (size_t)(e0 + r) * GPAD))[c8];
            *(uint4*)&ea_s[r * EA_STR + c8 * 8] = v;
        }
        __syncthreads();

        float4 acc[2][8];
        #pragma unroll
        for (int mi = 0; mi < 2; mi++)
            #pragma unroll
            for (int ni = 0; ni < 8; ni++)
                acc[mi][ni] = make_float4(0.f, 0.f, 0.f, 0.f);

        // ---- GEMM1: K=64 (4 k-tiles) ----
        #pragma unroll
        for (int kt = 0; kt < 4; kt++) {
            uint32_t a0[4], a1[4];
            ldsm4(a0, &ea_s[(mbase + lrow) * EA_STR + kt * 16 + lcol]);
            ldsm4(a1, &ea_s[(mbase + 16 + lrow) * EA_STR + kt * 16 + lcol]);
            #pragma unroll
            for (int ni = 0; ni < 8; ni++) {
                uint2 b = w1f[((nb + ni) * 4 + kt) * 32 + lid];
                mma16816(acc[0][ni], a0, b);
                mma16816(acc[1][ni], a1, b);
            }
        }

        // ---- ssp -> fp16 HID ----
        #pragma unroll
        for (int mi = 0; mi < 2; mi++) {
            int ra = mbase + mi * 16 + gid;
            int rb = ra + 8;
            #pragma unroll
            for (int ni = 0; ni < 8; ni++) {
                int c0 = (nb + ni) * 8 + 2 * tg;
                float4 v = acc[mi][ni];
                float ba = b1_s[c0], bb = b1_s[c0 + 1];
                *(uint32_t*)&hid_s[ra * HID_STR + c0] =
                    f2h2(sspf_fast(v.x + ba), sspf_fast(v.y + bb));
                *(uint32_t*)&hid_s[rb * HID_STR + c0] =
                    f2h2(sspf_fast(v.z + ba), sspf_fast(v.w + bb));
            }
        }
        __syncthreads();

        #pragma unroll
        for (int mi = 0; mi < 2; mi++)
            #pragma unroll
            for (int ni = 0; ni < 8; ni++)
                acc[mi][ni] = make_float4(0.f, 0.f, 0.f, 0.f);

        // ---- GEMM2: K=128 (8 k-tiles) ----
        #pragma unroll
        for (int kt = 0; kt < 8; kt++) {
            uint32_t a0[4], a1[4];
            ldsm4(a0, &hid_s[(mbase + lrow) * HID_STR + kt * 16 + lcol]);
            ldsm4(a1, &hid_s[(mbase + 16 + lrow) * HID_STR + kt * 16 + lcol]);
            #pragma unroll
            for (int ni = 0; ni < 8; ni++) {
                uint2 b = w2f[((nb + ni) * 8 + kt) * 32 + lid];
                mma16816(acc[0][ni], a0, b);
                mma16816(acc[1][ni], a1, b);
            }
        }

        // ---- epilogue: (C2 + b2) * C * xf[src] -> atomic agg[dst] ----
        #pragma unroll
        for (int mi = 0; mi < 2; mi++) {
            int ra = mbase + mi * 16 + gid;
            int rb = ra + 8;
            float Ca = C_s[ra], Cb = C_s[rb];
            const float* xa = &g_xf[(size_t)src_s[ra] * 128];
            const float* xb = &g_xf[(size_t)src_s[rb] * 128];
            float* ga = &g_agg[(size_t)dst_s[ra] * 128];
            float* gb = &g_agg[(size_t)dst_s[rb] * 128];
            #pragma unroll
            for (int ni = 0; ni < 8; ni++) {
                int c0 = (nb + ni) * 8 + 2 * tg;
                float4 v = acc[mi][ni];
                float2 bv = *(const float2*)&b2_s[c0];
                float2 xva = *(const float2*)&xa[c0];
                atomicAdd((float2*)&ga[c0],
                          make_float2((v.x + bv.x) * Ca * xva.x,
                                      (v.y + bv.y) * Ca * xva.y));
                float2 xvb = *(const float2*)&xb[c0];
                atomicAdd((float2*)&gb[c0],
                          make_float2((v.z + bv.x) * Cb * xvb.x,
                                      (v.w + bv.y) * Cb * xvb.y));
            }
        }
        __syncthreads();
    }
}

// ---------------- node update: h += lin(ssp(agg @ w2 + b2)) ----------------
__global__ __launch_bounds__(128) void node_update_kernel(
        const float* __restrict__ w2, const float* __restrict__ b2,
        const float* __restrict__ lw, const float* __restrict__ lb) {
    constexpr int NT = 16;
    extern __shared__ float sm[];
    float* w2_s = sm;
    float* lw_s = sm + 16384;
    __shared__ float in_s[NT * 128];
    __shared__ float x_s[NT * 128];
    int tid = threadIdx.x;
    for (int i = tid; i < 4096; i += 128) {
        ((float4*)w2_s)[i] = tf32r4(((const float4*)w2)[i]);
        ((float4*)lw_s)[i] = tf32r4(((const float4*)lw)[i]);
    }
    int n0 = blockIdx.x * NT;
    for (int i = tid; i < NT * 128 / 4; i += 128)
        ((float4*)in_s)[i] = tf32r4(((const float4*)&g_agg[(size_t)n0 * 128])[i]);
    __syncthreads();
    float acc[NT];
    float bb = b2[tid];
    #pragma unroll
    for (int e = 0; e < NT; e++) acc[e] = bb;
    #pragma unroll 4
    for (int k = 0; k < 128; k++) {
        float wv = w2_s[k * 128 + tid];
        #pragma unroll
        for (int e = 0; e < NT; e++)
            acc[e] = fmaf(in_s[e * 128 + k], wv, acc[e]);
    }
    #pragma unroll
    for (int e = 0; e < NT; e++)
        x_s[e * 128 + tid] = tf32r(sspf(acc[e]));
    __syncthreads();
    float lbb = lb[tid];
    #pragma unroll
    for (int e = 0; e < NT; e++) acc[e] = lbb;
    #pragma unroll 4
    for (int k = 0; k < 128; k++) {
        float wv = lw_s[k * 128 + tid];
        #pragma unroll
        for (int e = 0; e < NT; e++)
            acc[e] = fmaf(x_s[e * 128 + k], wv, acc[e]);
    }
    #pragma unroll
    for (int e = 0; e < NT; e++)
        g_h[(size_t)(n0 + e) * 128 + tid] += acc[e];
}

// ---------------- output head ----------------
__global__ __launch_bounds__(128) void out_kernel(
        const float* __restrict__ w1, const float* __restrict__ b1,
        const float* __restrict__ w2, const float* __restrict__ b2,
        const int* __restrict__ batch) {
    constexpr int NT = 16;
    extern __shared__ float sm[];
    float* w1_s = sm;
    float* w2_s = sm + 16384;
    __shared__ float in_s[NT * 128];
    __shared__ float x_s[NT * 128];
    int tid = threadIdx.x;
    for (int i = tid; i < 4096; i += 128) {
        ((float4*)w1_s)[i] = tf32r4(((const float4*)w1)[i]);
        ((float4*)w2_s)[i] = tf32r4(((const float4*)w2)[i]);
    }
    int n0 = blockIdx.x * NT;
    for (int i = tid; i < NT * 128 / 4; i += 128)
        ((float4*)in_s)[i] = tf32r4(((const float4*)&g_h[(size_t)n0 * 128])[i]);
    __syncthreads();
    float acc[NT];
    float bb1 = b1[tid];
    #pragma unroll
    for (int e = 0; e < NT; e++) acc[e] = bb1;
    #pragma unroll 4
    for (int k = 0; k < 128; k++) {
        float wv = w1_s[k * 128 + tid];
        #pragma unroll
        for (int e = 0; e < NT; e++)
            acc[e] = fmaf(in_s[e * 128 + k], wv, acc[e]);
    }
    #pragma unroll
    for (int e = 0; e < NT; e++)
        x_s[e * 128 + tid] = tf32r(sspf(acc[e]));
    __syncthreads();
    float bb2 = b2[tid];
    #pragma unroll
    for (int e = 0; e < NT; e++) acc[e] = bb2;
    #pragma unroll 4
    for (int k = 0; k < 128; k++) {
        float wv = w2_s[k * 128 + tid];
        #pragma unroll
        for (int e = 0; e < NT; e++)
            acc[e] = fmaf(x_s[e * 128 + k], wv, acc[e]);
    }
    #pragma unroll
    for (int e = 0; e < NT; e++) {
        int b = batch[n0 + e];
        atomicAdd(&g_sums[b * 128 + tid], acc[e]);
        if (tid == 0) atomicAdd(&g_cnt[b], 1.0f);
    }
}

__global__ void finalize_kernel(float* __restrict__ out) {
    int i = blockIdx.x * blockDim.x + threadIdx.x;
    if (i >= NGRAPH * HDIM) return;
    out[i] = g_sums[i] / fmaxf(g_cnt[i >> 7], 1.0f);
}

// ---------------- launcher ----------------
extern "C" void kernel_launch(void* const* d_in, const int* in_sizes, int n_in,
                              void* d_out, int out_size) {
    const int*   z       = (const int*)d_in[0];
    const float* pos     = (const float*)d_in[1];
    const int*   ei      = (const int*)d_in[2];
    const int*   batch   = (const int*)d_in[3];
    const float* emb     = (const float*)d_in[4];
    const float* mlp_w1  = (const float*)d_in[5];
    const float* mlp_b1  = (const float*)d_in[6];
    const float* mlp_w2  = (const float*)d_in[7];
    const float* mlp_b2  = (const float*)d_in[8];
    const float* conv_w1 = (const float*)d_in[9];
    const float* conv_w2 = (const float*)d_in[10];
    const float* conv_b2 = (const float*)d_in[11];
    const float* lin_w   = (const float*)d_in[12];
    const float* lin_b   = (const float*)d_in[13];
    const float* out1_w  = (const float*)d_in[14];
    const float* out1_b  = (const float*)d_in[15];
    const float* out2_w  = (const float*)d_in[16];
    const float* out2_b  = (const float*)d_in[17];
    float* out = (float*)d_out;

    const int* src = ei;
    const int* dst = ei + N_EDGES;

    // ea 18432 + hid 34816 + w1f 16384 + w2f 32768 + misc 2560 = 104960 B
    const int EDGE_SMEM = 104960;
    const int MV_SMEM   = 16384 * 4;
    const int NU_SMEM   = 32768 * 4;

    cudaFuncSetAttribute(edge_mma_kernel, cudaFuncAttributeMaxDynamicSharedMemorySize, EDGE_SMEM);
    cudaFuncSetAttribute(matvec_kernel, cudaFuncAttributeMaxDynamicSharedMemorySize, MV_SMEM);
    cudaFuncSetAttribute(node_update_kernel, cudaFuncAttributeMaxDynamicSharedMemorySize, NU_SMEM);
    cudaFuncSetAttribute(out_kernel, cudaFuncAttributeMaxDynamicSharedMemorySize, NU_SMEM);

    init_h_kernel<<<(N_NODES * HDIM + 255) / 256, 256>>>(z, emb);
    dist_kernel<<<(N_EDGES + 255) / 256, 256>>>(src, dst, pos);
    gauss_kernel<<<(N_EDGES * GPAD + 255) / 256, 256>>>();

    const int NODE_BLOCKS = N_NODES / 16;
    const int EDGE_GRID = 296;    // 2 blocks/SM

    for (int l = 0; l < NLAYERS; l++) {
        matvec_kernel<<<NODE_BLOCKS, 128, MV_SMEM>>>(conv_w1 + (size_t)l * 128 * 128);
        zero_agg_kernel<<<(N_NODES * HDIM + 255) / 256, 256>>>();
        edge_mma_kernel<<<EDGE_GRID, 256, EDGE_SMEM>>>(
            src, dst,
            mlp_w1 + (size_t)l * GDIM * 128, mlp_b1 + (size_t)l * 128,
            mlp_w2 + (size_t)l * 128 * 128,  mlp_b2 + (size_t)l * 128);
        node_update_kernel<<<NODE_BLOCKS, 128, NU_SMEM>>>(
            conv_w2 + (size_t)l * 128 * 128, conv_b2 + (size_t)l * 128,
            lin_w + (size_t)l * 128 * 128,   lin_b + (size_t)l * 128);
    }

    zero_sums_kernel<<<(NGRAPH * HDIM + 255) / 256, 256>>>();
    out_kernel<<<NODE_BLOCKS, 128, NU_SMEM>>>(out1_w, out1_b, out2_w, out2_b, batch);
    finalize_kernel<<<(NGRAPH * HDIM + 255) / 256, 256>>>(out);
}

// round 6
// speedup vs baseline: 5.4824x; 1.5768x over previous
#include <cuda_runtime.h>
#include <cuda_fp16.h>
#include <math.h>
#include <stdint.h>

#define N_NODES 20000
#define N_EDGES 640000
#define HDIM    128
#define GDIM    50
#define GPAD    64
#define NLAYERS 6
#define NGRAPH  64
#define CUTOFF  10.0f
#define LOG2F_  0.69314718055994531f
#define PI_     3.14159265358979323846f

#define EPT     128
#define NTILES  (N_EDGES / EPT)
#define EA_STR  72        // halves/row
#define HID_STR 136       // halves/row
#define MSTR    132       // msg floats/row

// ---------------- device scratch ----------------
static __device__ __align__(16) float  g_h[N_NODES * HDIM];
static __device__ __align__(16) float  g_xf[N_NODES * HDIM];
static __device__ __align__(16) float  g_agg[N_NODES * HDIM];
static __device__ __align__(16) float  g_d[N_EDGES];
static __device__ __align__(16) float  g_C[N_EDGES];
static __device__ __align__(16) __half g_ea[(size_t)N_EDGES * GPAD]; // PERMUTED order
static __device__ __align__(16) float  g_sums[NGRAPH * HDIM];
static __device__ float g_cnt[NGRAPH];
// sorting scratch
static __device__ int   g_hist[N_NODES];
static __device__ int   g_perm[N_EDGES];
static __device__ int   g_srcp[N_EDGES];
static __device__ int   g_dstp[N_EDGES];
static __device__ float g_Cp[N_EDGES];

// ---------------- helpers ----------------
__device__ __forceinline__ float tf32r(float x) {
    uint32_t r;
    asm("cvt.rna.tf32.f32 %0, %1;" : "=r"(r) : "f"(x));
    return __uint_as_float(r);
}
__device__ __forceinline__ float4 tf32r4(float4 v) {
    v.x = tf32r(v.x); v.y = tf32r(v.y); v.z = tf32r(v.z); v.w = tf32r(v.w);
    return v;
}
__device__ __forceinline__ float sspf(float x) {
    return fmaxf(x, 0.f) + log1pf(expf(-fabsf(x))) - LOG2F_;
}
__device__ __forceinline__ float sspf_fast(float x) {
    return fmaxf(x, 0.f) + __logf(1.f + __expf(-fabsf(x))) - LOG2F_;
}
__device__ __forceinline__ uint32_t smem_u32(const void* p) {
    uint32_t a;
    asm("{ .reg .u64 t; cvta.to.shared.u64 t, %1; cvt.u32.u64 %0, t; }" : "=r"(a) : "l"(p));
    return a;
}
__device__ __forceinline__ uint32_t f2h2(float lo, float hi) {
    __half2 h = __floats2half2_rn(lo, hi);
    return *reinterpret_cast<uint32_t*>(&h);
}
__device__ __forceinline__ void mma16816(float4& d, const uint32_t a[4], uint2 b) {
    asm volatile(
        "mma.sync.aligned.m16n8k16.row.col.f32.f16.f16.f32 "
        "{%0,%1,%2,%3}, {%4,%5,%6,%7}, {%8,%9}, {%0,%1,%2,%3};\n"
        : "+f"(d.x), "+f"(d.y), "+f"(d.z), "+f"(d.w)
        : "r"(a[0]), "r"(a[1]), "r"(a[2]), "r"(a[3]), "r"(b.x), "r"(b.y));
}
__device__ __forceinline__ void ldsm4(uint32_t r[4], const void* p) {
    uint32_t a = smem_u32(p);
    asm volatile("ldmatrix.sync.aligned.m8n8.x4.shared.b16 {%0,%1,%2,%3}, [%4];"
        : "=r"(r[0]), "=r"(r[1]), "=r"(r[2]), "=r"(r[3]) : "r"(a));
}

// ---------------- precompute ----------------
__global__ void init_h_kernel(const int* __restrict__ z, const float* __restrict__ emb) {
    int i = blockIdx.x * blockDim.x + threadIdx.x;
    if (i >= N_NODES * HDIM) return;
    int n = i >> 7, j = i & 127;
    g_h[i] = emb[z[n] * HDIM + j];
}

__global__ void dist_kernel(const int* __restrict__ src, const int* __restrict__ dst,
                            const float* __restrict__ pos) {
    int e = blockIdx.x * blockDim.x + threadIdx.x;
    if (e >= N_EDGES) return;
    int s = src[e], t = dst[e];
    float dx = pos[s * 3 + 0] - pos[t * 3 + 0];
    float dy = pos[s * 3 + 1] - pos[t * 3 + 1];
    float dz = pos[s * 3 + 2] - pos[t * 3 + 2];
    float d = sqrtf(dx * dx + dy * dy + dz * dz);
    g_d[e] = d;
    g_C[e] = 0.5f * (cosf(d * (PI_ / CUTOFF)) + 1.0f);
}

__global__ void zero_hist_kernel() {
    int i = blockIdx.x * blockDim.x + threadIdx.x;
    if (i < N_NODES) g_hist[i] = 0;
}
__global__ void hist_kernel(const int* __restrict__ dst) {
    int e = blockIdx.x * blockDim.x + threadIdx.x;
    if (e < N_EDGES) atomicAdd(&g_hist[dst[e]], 1);
}
__global__ void scan_kernel() {   // 1 block, 1024 threads: exclusive scan of g_hist
    __shared__ int s[1024];
    int t = threadIdx.x;
    const int CH = (N_NODES + 1023) / 1024;   // 20
    int base = t * CH;
    int sum = 0;
    for (int i = 0; i < CH; i++) {
        int idx = base + i;
        if (idx < N_NODES) sum += g_hist[idx];
    }
    s[t] = sum;
    __syncthreads();
    for (int off = 1; off < 1024; off <<= 1) {
        int v = (t >= off) ? s[t - off] : 0;
        __syncthreads();
        s[t] += v;
        __syncthreads();
    }
    int run = (t > 0) ? s[t - 1] : 0;
    for (int i = 0; i < CH; i++) {
        int idx = base + i;
        if (idx < N_NODES) { int c = g_hist[idx]; g_hist[idx] = run; run += c; }
    }
}
__global__ void scatter_kernel(const int* __restrict__ src, const int* __restrict__ dst) {
    int e = blockIdx.x * blockDim.x + threadIdx.x;
    if (e >= N_EDGES) return;
    int d = dst[e];
    int p = atomicAdd(&g_hist[d], 1);
    g_perm[p] = e;
    g_srcp[p] = src[e];
    g_dstp[p] = d;
    g_Cp[p]   = g_C[e];
}
__global__ void gauss_kernel() {   // permuted order
    int i = blockIdx.x * blockDim.x + threadIdx.x;
    if (i >= N_EDGES * GPAD) return;
    int e = i >> 6, c = i & 63;
    const float step = CUTOFF / (GDIM - 1);
    const float coeff = -0.5f / (step * step);
    float v = 0.f;
    if (c < GDIM) {
        float diff = g_d[g_perm[e]] - c * step;
        v = __expf(coeff * diff * diff);
    }
    g_ea[i] = __float2half_rn(v);
}

// ---------------- initial xf = h @ conv_w1[0] ----------------
__global__ __launch_bounds__(128) void matvec_kernel(const float* __restrict__ w) {
    constexpr int NT = 16;
    extern __shared__ float w_s[];
    __shared__ float in_s[NT * 128];
    int tid = threadIdx.x;
    for (int i = tid; i < 16384 / 4; i += 128)
        ((float4*)w_s)[i] = tf32r4(((const float4*)w)[i]);
    int n0 = blockIdx.x * NT;
    for (int i = tid; i < NT * 128 / 4; i += 128)
        ((float4*)in_s)[i] = tf32r4(((const float4*)&g_h[(size_t)n0 * 128])[i]);
    __syncthreads();
    float acc[NT];
    #pragma unroll
    for (int e = 0; e < NT; e++) acc[e] = 0.f;
    #pragma unroll 4
    for (int k = 0; k < 128; k++) {
        float wv = w_s[k * 128 + tid];
        #pragma unroll
        for (int e = 0; e < NT; e++)
            acc[e] = fmaf(in_s[e * 128 + k], wv, acc[e]);
    }
    #pragma unroll
    for (int e = 0; e < NT; e++)
        g_xf[(size_t)(n0 + e) * 128 + tid] = acc[e];
}

__global__ void zero_agg_kernel() {
    int i = blockIdx.x * blockDim.x + threadIdx.x;
    if (i < N_NODES * HDIM) g_agg[i] = 0.f;
}
__global__ void zero_sums_kernel() {
    int i = blockIdx.x * blockDim.x + threadIdx.x;
    if (i < NGRAPH * HDIM) g_sums[i] = 0.f;
    if (i < NGRAPH) g_cnt[i] = 0.f;
}

// ---------------- fp16 MMA edge kernel (dst-sorted, staged reduction) ------
__global__ __launch_bounds__(256, 2) void edge_mma_kernel(
        const float* __restrict__ w1, const float* __restrict__ b1,
        const float* __restrict__ w2, const float* __restrict__ b2) {
    extern __shared__ char smraw[];
    __half* ea_s  = (__half*)smraw;                   // 18432 B
    __half* hid_s = (__half*)(smraw + 18432);         // 34816 B
    float*  msg   = (float*)smraw;                    // 64*132*4 = 33792 B (aliases ea+hid)
    uint2*  w1f   = (uint2*)(smraw + 53248);          // 16384 B
    uint2*  w2f   = (uint2*)(smraw + 69632);          // 32768 B
    float*  b1_s  = (float*)(smraw + 102400);         // 128
    float*  b2_s  = b1_s + 128;
    float*  C_s   = b2_s + 128;
    int*    src_s = (int*)(C_s + 128);
    int*    dst_s = src_s + 128;

    int tid = threadIdx.x;
    int wid = tid >> 5;
    int lid = tid & 31;
    int gid = lid >> 2;
    int tg  = lid & 3;
    int lrow = lid & 15;
    int lcol = (lid >> 4) << 3;

    if (tid < 128) { b1_s[tid] = b1[tid]; b2_s[tid] = b2[tid]; }
    for (int i = tid; i < 2048; i += 256) {
        int l = i & 31, kt = (i >> 5) & 3, nt = i >> 7;
        int g_ = l >> 2, t_ = l & 3;
        int k0 = kt * 16 + 2 * t_, n = nt * 8 + g_;
        float v0 = (k0     < GDIM) ? w1[k0 * 128 + n]       : 0.f;
        float v1 = (k0 + 1 < GDIM) ? w1[(k0 + 1) * 128 + n] : 0.f;
        float v2 = (k0 + 8 < GDIM) ? w1[(k0 + 8) * 128 + n] : 0.f;
        float v3 = (k0 + 9 < GDIM) ? w1[(k0 + 9) * 128 + n] : 0.f;
        w1f[i] = make_uint2(f2h2(v0, v1), f2h2(v2, v3));
    }
    for (int i = tid; i < 4096; i += 256) {
        int l = i & 31, kt = (i >> 5) & 7, nt = i >> 8;
        int g_ = l >> 2, t_ = l & 3;
        int k0 = kt * 16 + 2 * t_, n = nt * 8 + g_;
        w2f[i] = make_uint2(f2h2(w2[k0 * 128 + n], w2[(k0 + 1) * 128 + n]),
                            f2h2(w2[(k0 + 8) * 128 + n], w2[(k0 + 9) * 128 + n]));
    }
    __syncthreads();

    int mbase = (wid & 3) * 32;
    int nb    = (wid >> 2) * 8;

    for (int t = blockIdx.x; t < NTILES; t += gridDim.x) {
        int e0 = t * EPT;
        if (tid < 128) {
            src_s[tid] = g_srcp[e0 + tid];
            dst_s[tid] = g_dstp[e0 + tid];
            C_s[tid]   = g_Cp[e0 + tid];
        }
        for (int i = tid; i < 1024; i += 256) {
            int r = i >> 3, c8 = i & 7;
            uint4 v = ((const uint4*)(g_ea + (size_t)(e0 + r) * GPAD))[c8];
            *(uint4*)&ea_s[r * EA_STR + c8 * 8] = v;
        }
        __syncthreads();

        float4 acc[2][8];
        #pragma unroll
        for (int mi = 0; mi < 2; mi++)
            #pragma unroll
            for (int ni = 0; ni < 8; ni++)
                acc[mi][ni] = make_float4(0.f, 0.f, 0.f, 0.f);

        // GEMM1: K=64
        #pragma unroll
        for (int kt = 0; kt < 4; kt++) {
            uint32_t a0[4], a1[4];
            ldsm4(a0, &ea_s[(mbase + lrow) * EA_STR + kt * 16 + lcol]);
            ldsm4(a1, &ea_s[(mbase + 16 + lrow) * EA_STR + kt * 16 + lcol]);
            #pragma unroll
            for (int ni = 0; ni < 8; ni++) {
                uint2 b = w1f[((nb + ni) * 4 + kt) * 32 + lid];
                mma16816(acc[0][ni], a0, b);
                mma16816(acc[1][ni], a1, b);
            }
        }

        // ssp -> fp16 HID
        #pragma unroll
        for (int mi = 0; mi < 2; mi++) {
            int ra = mbase + mi * 16 + gid;
            int rb = ra + 8;
            #pragma unroll
            for (int ni = 0; ni < 8; ni++) {
                int c0 = (nb + ni) * 8 + 2 * tg;
                float4 v = acc[mi][ni];
                float ba = b1_s[c0], bb = b1_s[c0 + 1];
                *(uint32_t*)&hid_s[ra * HID_STR + c0] =
                    f2h2(sspf_fast(v.x + ba), sspf_fast(v.y + bb));
                *(uint32_t*)&hid_s[rb * HID_STR + c0] =
                    f2h2(sspf_fast(v.z + ba), sspf_fast(v.w + bb));
            }
        }
        __syncthreads();

        #pragma unroll
        for (int mi = 0; mi < 2; mi++)
            #pragma unroll
            for (int ni = 0; ni < 8; ni++)
                acc[mi][ni] = make_float4(0.f, 0.f, 0.f, 0.f);

        // GEMM2: K=128
        #pragma unroll
        for (int kt = 0; kt < 8; kt++) {
            uint32_t a0[4], a1[4];
            ldsm4(a0, &hid_s[(mbase + lrow) * HID_STR + kt * 16 + lcol]);
            ldsm4(a1, &hid_s[(mbase + 16 + lrow) * HID_STR + kt * 16 + lcol]);
            #pragma unroll
            for (int ni = 0; ni < 8; ni++) {
                uint2 b = w2f[((nb + ni) * 8 + kt) * 32 + lid];
                mma16816(acc[0][ni], a0, b);
                mma16816(acc[1][ni], a1, b);
            }
        }
        __syncthreads();   // all warps done reading hid before msg overwrite

        // epilogue: stage scaled msgs, segmented-reduce (dst sorted), float4 atomics
        #pragma unroll
        for (int mi = 0; mi < 2; mi++) {
            int ra = mbase + mi * 16 + gid;
            int rb = ra + 8;
            int ba = (wid & 3) * 16 + gid;
            int bbr = ba + 8;
            float Ca = C_s[ra], Cb = C_s[rb];
            const float* xa = &g_xf[(size_t)src_s[ra] * 128];
            const float* xb = &g_xf[(size_t)src_s[rb] * 128];
            #pragma unroll
            for (int ni = 0; ni < 8; ni++) {
                int c0 = (nb + ni) * 8 + 2 * tg;
                float4 v = acc[mi][ni];
                float2 bv = *(const float2*)&b2_s[c0];
                float2 xva = *(const float2*)&xa[c0];
                float2 xvb = *(const float2*)&xb[c0];
                *(float2*)&msg[ba * MSTR + c0] =
                    make_float2((v.x + bv.x) * Ca * xva.x, (v.y + bv.y) * Ca * xva.y);
                *(float2*)&msg[bbr * MSTR + c0] =
                    make_float2((v.z + bv.x) * Cb * xvb.x, (v.w + bv.y) * Cb * xvb.y);
            }
            __syncthreads();
            if (tid < 128) {
                int cg = tid & 31;
                int rc = tid >> 5;             // 0..3 (strip)
                int b0 = rc * 16;
                int r0 = rc * 32 + mi * 16;    // edge row base
                float4 run = make_float4(0.f, 0.f, 0.f, 0.f);
                int cur = dst_s[r0];
                #pragma unroll
                for (int j = 0; j < 16; j++) {
                    int d = dst_s[r0 + j];
                    float4 v = *(float4*)&msg[(b0 + j) * MSTR + cg * 4];
                    if (d != cur) {
                        atomicAdd((float4*)&g_agg[(size_t)cur * 128 + cg * 4], run);
                        run = make_float4(0.f, 0.f, 0.f, 0.f);
                        cur = d;
                    }
                    run.x += v.x; run.y += v.y; run.z += v.z; run.w += v.w;
                }
                atomicAdd((float4*)&g_agg[(size_t)cur * 128 + cg * 4], run);
            }
            __syncthreads();
        }
    }
}

// ---------------- fused node kernel ----------------
// x = ssp(agg @ wA + bA); h += x @ wB + bB; if(do_c) xf = h @ wC
__global__ __launch_bounds__(256, 1) void node_fused_kernel(
        const float* __restrict__ wA, const float* __restrict__ bA,
        const float* __restrict__ wB, const float* __restrict__ bB,
        const float* __restrict__ wC, int do_c) {
    extern __shared__ char smraw[];
    __half* in_s = (__half*)smraw;               // 34816 (also h_s)
    __half* x_s  = (__half*)(smraw + 34816);     // 34816
    uint2*  wAf  = (uint2*)(smraw + 69632);      // 32768
    uint2*  wBf  = (uint2*)(smraw + 102400);     // 32768
    uint2*  wCf  = (uint2*)(smraw + 135168);     // 32768
    float*  bA_s = (float*)(smraw + 167936);
    float*  bB_s = bA_s + 128;

    int tid = threadIdx.x;
    int wid = tid >> 5;
    int lid = tid & 31;
    int gid = lid >> 2;
    int tg  = lid & 3;
    int lrow = lid & 15;
    int lcol = (lid >> 4) << 3;

    if (tid < 128) { bA_s[tid] = bA[tid]; bB_s[tid] = bB[tid]; }
    for (int i = tid; i < 4096; i += 256) {
        int l = i & 31, kt = (i >> 5) & 7, nt = i >> 8;
        int g_ = l >> 2, t_ = l & 3;
        int k0 = kt * 16 + 2 * t_, n = nt * 8 + g_;
        wAf[i] = make_uint2(f2h2(wA[k0 * 128 + n], wA[(k0 + 1) * 128 + n]),
                            f2h2(wA[(k0 + 8) * 128 + n], wA[(k0 + 9) * 128 + n]));
        wBf[i] = make_uint2(f2h2(wB[k0 * 128 + n], wB[(k0 + 1) * 128 + n]),
                            f2h2(wB[(k0 + 8) * 128 + n], wB[(k0 + 9) * 128 + n]));
        if (do_c)
            wCf[i] = make_uint2(f2h2(wC[k0 * 128 + n], wC[(k0 + 1) * 128 + n]),
                                f2h2(wC[(k0 + 8) * 128 + n], wC[(k0 + 9) * 128 + n]));
    }

    int n0 = blockIdx.x * 128;
    // stage agg -> fp16
    for (int i = tid; i < 128 * 32; i += 256) {
        int r = i >> 5, c4 = i & 31;
        float4 v = make_float4(0.f, 0.f, 0.f, 0.f);
        if (n0 + r < N_NODES)
            v = ((const float4*)&g_agg[(size_t)(n0 + r) * 128])[c4];
        *(uint2*)&in_s[r * HID_STR + c4 * 4] = make_uint2(f2h2(v.x, v.y), f2h2(v.z, v.w));
    }
    __syncthreads();

    int mbase = (wid & 3) * 32;
    int nb    = (wid >> 2) * 8;

    float4 acc[2][8];
    // ---- GEMM A: x = ssp(agg @ wA + bA) ----
    #pragma unroll
    for (int mi = 0; mi < 2; mi++)
        #pragma unroll
        for (int ni = 0; ni < 8; ni++)
            acc[mi][ni] = make_float4(0.f, 0.f, 0.f, 0.f);
    #pragma unroll
    for (int kt = 0; kt < 8; kt++) {
        uint32_t a0[4], a1[4];
        ldsm4(a0, &in_s[(mbase + lrow) * HID_STR + kt * 16 + lcol]);
        ldsm4(a1, &in_s[(mbase + 16 + lrow) * HID_STR + kt * 16 + lcol]);
        #pragma unroll
        for (int ni = 0; ni < 8; ni++) {
            uint2 b = wAf[((nb + ni) * 8 + kt) * 32 + lid];
            mma16816(acc[0][ni], a0, b);
            mma16816(acc[1][ni], a1, b);
        }
    }
    #pragma unroll
    for (int mi = 0; mi < 2; mi++) {
        int ra = mbase + mi * 16 + gid;
        int rb = ra + 8;
        #pragma unroll
        for (int ni = 0; ni < 8; ni++) {
            int c0 = (nb + ni) * 8 + 2 * tg;
            float4 v = acc[mi][ni];
            float ba = bA_s[c0], bb = bA_s[c0 + 1];
            *(uint32_t*)&x_s[ra * HID_STR + c0] =
                f2h2(sspf_fast(v.x + ba), sspf_fast(v.y + bb));
            *(uint32_t*)&x_s[rb * HID_STR + c0] =
                f2h2(sspf_fast(v.z + ba), sspf_fast(v.w + bb));
        }
    }
    __syncthreads();

    // ---- GEMM B: h += x @ wB + bB ----
    #pragma unroll
    for (int mi = 0; mi < 2; mi++)
        #pragma unroll
        for (int ni = 0; ni < 8; ni++)
            acc[mi][ni] = make_float4(0.f, 0.f, 0.f, 0.f);
    #pragma unroll
    for (int kt = 0; kt < 8; kt++) {
        uint32_t a0[4], a1[4];
        ldsm4(a0, &x_s[(mbase + lrow) * HID_STR + kt * 16 + lcol]);
        ldsm4(a1, &x_s[(mbase + 16 + lrow) * HID_STR + kt * 16 + lcol]);
        #pragma unroll
        for (int ni = 0; ni < 8; ni++) {
            uint2 b = wBf[((nb + ni) * 8 + kt) * 32 + lid];
            mma16816(acc[0][ni], a0, b);
            mma16816(acc[1][ni], a1, b);
        }
    }
    #pragma unroll
    for (int mi = 0; mi < 2; mi++) {
        int ra = mbase + mi * 16 + gid;
        int rb = ra + 8;
        int na = n0 + ra, nbn = n0 + rb;
        #pragma unroll
        for (int ni = 0; ni < 8; ni++) {
            int c0 = (nb + ni) * 8 + 2 * tg;
            float4 v = acc[mi][ni];
            float ba = bB_s[c0], bb = bB_s[c0 + 1];
            float hx = 0.f, hy = 0.f, hz = 0.f, hw = 0.f;
            if (na < N_NODES) {
                float2 hv = *(float2*)&g_h[(size_t)na * 128 + c0];
                hx = hv.x + v.x + ba;
                hy = hv.y + v.y + bb;
                *(float2*)&g_h[(size_t)na * 128 + c0] = make_float2(hx, hy);
            }
            if (nbn < N_NODES) {
                float2 hv = *(float2*)&g_h[(size_t)nbn * 128 + c0];
                hz = hv.x + v.z + ba;
                hw = hv.y + v.w + bb;
                *(float2*)&g_h[(size_t)nbn * 128 + c0] = make_float2(hz, hw);
            }
            *(uint32_t*)&in_s[ra * HID_STR + c0] = f2h2(hx, hy);
            *(uint32_t*)&in_s[rb * HID_STR + c0] = f2h2(hz, hw);
        }
    }
    __syncthreads();

    if (!do_c) return;

    // ---- GEMM C: xf = h @ wC ----
    #pragma unroll
    for (int mi = 0; mi < 2; mi++)
        #pragma unroll
        for (int ni = 0; ni < 8; ni++)
            acc[mi][ni] = make_float4(0.f, 0.f, 0.f, 0.f);
    #pragma unroll
    for (int kt = 0; kt < 8; kt++) {
        uint32_t a0[4], a1[4];
        ldsm4(a0, &in_s[(mbase + lrow) * HID_STR + kt * 16 + lcol]);
        ldsm4(a1, &in_s[(mbase + 16 + lrow) * HID_STR + kt * 16 + lcol]);
        #pragma unroll
        for (int ni = 0; ni < 8; ni++) {
            uint2 b = wCf[((nb + ni) * 8 + kt) * 32 + lid];
            mma16816(acc[0][ni], a0, b);
            mma16816(acc[1][ni], a1, b);
        }
    }
    #pragma unroll
    for (int mi = 0; mi < 2; mi++) {
        int ra = mbase + mi * 16 + gid;
        int rb = ra + 8;
        int na = n0 + ra, nbn = n0 + rb;
        #pragma unroll
        for (int ni = 0; ni < 8; ni++) {
            int c0 = (nb + ni) * 8 + 2 * tg;
            float4 v = acc[mi][ni];
            if (na < N_NODES)
                *(float2*)&g_xf[(size_t)na * 128 + c0] = make_float2(v.x, v.y);
            if (nbn < N_NODES)
                *(float2*)&g_xf[(size_t)nbn * 128 + c0] = make_float2(v.z, v.w);
        }
    }
}

// ---------------- output head ----------------
__global__ __launch_bounds__(128) void out_kernel(
        const float* __restrict__ w1, const float* __restrict__ b1,
        const float* __restrict__ w2, const float* __restrict__ b2,
        const int* __restrict__ batch) {
    constexpr int NT = 16;
    extern __shared__ float sm[];
    float* w1_s = sm;
    float* w2_s = sm + 16384;
    __shared__ float in_s[NT * 128];
    __shared__ float x_s[NT * 128];
    int tid = threadIdx.x;
    for (int i = tid; i < 4096; i += 128) {
        ((float4*)w1_s)[i] = tf32r4(((const float4*)w1)[i]);
        ((float4*)w2_s)[i] = tf32r4(((const float4*)w2)[i]);
    }
    int n0 = blockIdx.x * NT;
    for (int i = tid; i < NT * 128 / 4; i += 128)
        ((float4*)in_s)[i] = tf32r4(((const float4*)&g_h[(size_t)n0 * 128])[i]);
    __syncthreads();
    float acc[NT];
    float bb1 = b1[tid];
    #pragma unroll
    for (int e = 0; e < NT; e++) acc[e] = bb1;
    #pragma unroll 4
    for (int k = 0; k < 128; k++) {
        float wv = w1_s[k * 128 + tid];
        #pragma unroll
        for (int e = 0; e < NT; e++)
            acc[e] = fmaf(in_s[e * 128 + k], wv, acc[e]);
    }
    #pragma unroll
    for (int e = 0; e < NT; e++)
        x_s[e * 128 + tid] = tf32r(sspf(acc[e]));
    __syncthreads();
    float bb2 = b2[tid];
    #pragma unroll
    for (int e = 0; e < NT; e++) acc[e] = bb2;
    #pragma unroll 4
    for (int k = 0; k < 128; k++) {
        float wv = w2_s[k * 128 + tid];
        #pragma unroll
        for (int e = 0; e < NT; e++)
            acc[e] = fmaf(x_s[e * 128 + k], wv, acc[e]);
    }
    #pragma unroll
    for (int e = 0; e < NT; e++) {
        int b = batch[n0 + e];
        atomicAdd(&g_sums[b * 128 + tid], acc[e]);
        if (tid == 0) atomicAdd(&g_cnt[b], 1.0f);
    }
}

__global__ void finalize_kernel(float* __restrict__ out) {
    int i = blockIdx.x * blockDim.x + threadIdx.x;
    if (i >= NGRAPH * HDIM) return;
    out[i] = g_sums[i] / fmaxf(g_cnt[i >> 7], 1.0f);
}

// ---------------- launcher ----------------
extern "C" void kernel_launch(void* const* d_in, const int* in_sizes, int n_in,
                              void* d_out, int out_size) {
    const int*   z       = (const int*)d_in[0];
    const float* pos     = (const float*)d_in[1];
    const int*   ei      = (const int*)d_in[2];
    const int*   batch   = (const int*)d_in[3];
    const float* emb     = (const float*)d_in[4];
    const float* mlp_w1  = (const float*)d_in[5];
    const float* mlp_b1  = (const float*)d_in[6];
    const float* mlp_w2  = (const float*)d_in[7];
    const float* mlp_b2  = (const float*)d_in[8];
    const float* conv_w1 = (const float*)d_in[9];
    const float* conv_w2 = (const float*)d_in[10];
    const float* conv_b2 = (const float*)d_in[11];
    const float* lin_w   = (const float*)d_in[12];
    const float* lin_b   = (const float*)d_in[13];
    const float* out1_w  = (const float*)d_in[14];
    const float* out1_b  = (const float*)d_in[15];
    const float* out2_w  = (const float*)d_in[16];
    const float* out2_b  = (const float*)d_in[17];
    float* out = (float*)d_out;

    const int* src = ei;
    const int* dst = ei + N_EDGES;

    const int EDGE_SMEM = 104960;
    const int NODE_SMEM = 168960;
    const int MV_SMEM   = 16384 * 4;
    const int NU_SMEM   = 32768 * 4;

    cudaFuncSetAttribute(edge_mma_kernel, cudaFuncAttributeMaxDynamicSharedMemorySize, EDGE_SMEM);
    cudaFuncSetAttribute(node_fused_kernel, cudaFuncAttributeMaxDynamicSharedMemorySize, NODE_SMEM);
    cudaFuncSetAttribute(matvec_kernel, cudaFuncAttributeMaxDynamicSharedMemorySize, MV_SMEM);
    cudaFuncSetAttribute(out_kernel, cudaFuncAttributeMaxDynamicSharedMemorySize, NU_SMEM);

    // precompute + edge sort (by dst)
    init_h_kernel<<<(N_NODES * HDIM + 255) / 256, 256>>>(z, emb);
    dist_kernel<<<(N_EDGES + 255) / 256, 256>>>(src, dst, pos);
    zero_hist_kernel<<<(N_NODES + 255) / 256, 256>>>();
    hist_kernel<<<(N_EDGES + 255) / 256, 256>>>(dst);
    scan_kernel<<<1, 1024>>>();
    scatter_kernel<<<(N_EDGES + 255) / 256, 256>>>(src, dst);
    gauss_kernel<<<(N_EDGES * GPAD + 255) / 256, 256>>>();

    matvec_kernel<<<N_NODES / 16, 128, MV_SMEM>>>(conv_w1);   // xf for layer 0

    const int NODE_BLOCKS = (N_NODES + 127) / 128;            // 157
    for (int l = 0; l < NLAYERS; l++) {
        zero_agg_kernel<<<(N_NODES * HDIM + 255) / 256, 256>>>();
        edge_mma_kernel<<<296, 256, EDGE_SMEM>>>(
            mlp_w1 + (size_t)l * GDIM * 128, mlp_b1 + (size_t)l * 128,
            mlp_w2 + (size_t)l * 128 * 128,  mlp_b2 + (size_t)l * 128);
        int do_c = (l < NLAYERS - 1) ? 1 : 0;
        node_fused_kernel<<<NODE_BLOCKS, 256, NODE_SMEM>>>(
            conv_w2 + (size_t)l * 128 * 128, conv_b2 + (size_t)l * 128,
            lin_w + (size_t)l * 128 * 128,   lin_b + (size_t)l * 128,
            conv_w1 + (size_t)(do_c ? (l + 1) : 0) * 128 * 128, do_c);
    }

    zero_sums_kernel<<<(NGRAPH * HDIM + 255) / 256, 256>>>();
    out_kernel<<<N_NODES / 16, 128, NU_SMEM>>>(out1_w, out1_b, out2_w, out2_b, batch);
    finalize_kernel<<<(NGRAPH * HDIM + 255) / 256, 256>>>(out);
}